// round 10
// baseline (speedup 1.0000x reference)
#include <cuda_runtime.h>

// GatedCNNLayer: X (16,4096,1024) f32, G (1024,2) f32, Gb (2,) f32
// out[b,p,:] = X[b,2p,:]*g0 + X[b,2p+2,:]*g1,
//   g = softmax(X[b,2p+1,:] @ G + Gb), p in [0,2047)
//
// R3 body (warp-per-pair, front-batched loads, warp-only reduce, smem G)
// with L/R rows loaded via plain 256-bit ld.global.nc.v8.b32 (default L2
// policy — preserves the incidental even-row L2 dedup; halves L/R LDG count).
// Mids __ldcs (read-once), output __stcs (streaming).

#define BATCH 16
#define SEQ   4096
#define DIM   1024
#define D4    (DIM / 4)      // 256 float4 per row
#define PAIRS 2047
#define WPB   8              // warps (pairs) per block
#define NBLKX ((PAIRS + WPB - 1) / WPB)   // 256

// plain 256-bit load: two consecutive float4s, default cache policy
__device__ __forceinline__ void ld256(const float4* p, float4& a, float4& b)
{
    unsigned r0, r1, r2, r3, r4, r5, r6, r7;
    asm("ld.global.nc.v8.b32 {%0,%1,%2,%3,%4,%5,%6,%7}, [%8];"
        : "=r"(r0), "=r"(r1), "=r"(r2), "=r"(r3),
          "=r"(r4), "=r"(r5), "=r"(r6), "=r"(r7)
        : "l"(p));
    a.x = __uint_as_float(r0); a.y = __uint_as_float(r1);
    a.z = __uint_as_float(r2); a.w = __uint_as_float(r3);
    b.x = __uint_as_float(r4); b.y = __uint_as_float(r5);
    b.z = __uint_as_float(r6); b.w = __uint_as_float(r7);
}

__global__ __launch_bounds__(256)
void gated_cnn_v8_kernel(const float* __restrict__ X,
                         const float* __restrict__ G,
                         const float* __restrict__ Gb,
                         float* __restrict__ out)
{
    __shared__ float4 Gsh[2 * D4];   // 8 KB, (d,2) interleaved as float4 pairs

    const int t    = threadIdx.x;
    const int warp = t >> 5;
    const int lane = t & 31;

    // Stage G once per block (cold path, single barrier)
    {
        const float4* __restrict__ G4 = (const float4*)G;
        Gsh[t]       = G4[t];
        Gsh[t + 256] = G4[t + 256];
    }
    __syncthreads();

    const int p = blockIdx.x * WPB + warp;
    if (p >= PAIRS) return;
    const int b = blockIdx.y;

    const float4* __restrict__ X4 = (const float4*)X;
    float4* __restrict__ O4 = (float4*)out;

    const size_t rowL = ((size_t)b * SEQ + (size_t)(2 * p)) * D4;   // f4 units
    const size_t rowM = rowL + D4;
    const size_t rowR = rowM + D4;

    // ---- front-batched loads ----
    // mids: 8 x LDG.128 streaming (read-once)
    float4 M[8];
    #pragma unroll
    for (int j = 0; j < 8; j++) M[j] = __ldcs(&X4[rowM + j * 32 + lane]);

    // left/right: 4 x LDG.256 each (32B per lane, default policy)
    float4 L[8], R[8];
    #pragma unroll
    for (int j = 0; j < 4; j++)
        ld256(&X4[rowL + j * 64 + 2 * lane], L[2 * j], L[2 * j + 1]);
    #pragma unroll
    for (int j = 0; j < 4; j++)
        ld256(&X4[rowR + j * 64 + 2 * lane], R[2 * j], R[2 * j + 1]);

    // ---- gate logits from mids (smem-resident G) ----
    float s0 = 0.f, s1 = 0.f;
    #pragma unroll
    for (int j = 0; j < 8; j++) {
        const int idx = j * 32 + lane;
        const float4 m  = M[j];
        const float4 ga = Gsh[2 * idx];
        const float4 gc = Gsh[2 * idx + 1];
        s0 += m.x * ga.x + m.y * ga.z + m.z * gc.x + m.w * gc.z;
        s1 += m.x * ga.y + m.y * ga.w + m.z * gc.y + m.w * gc.w;
    }

    // ---- warp-only reduction (no block barrier) ----
    #pragma unroll
    for (int off = 16; off > 0; off >>= 1) {
        s0 += __shfl_xor_sync(0xFFFFFFFFu, s0, off);
        s1 += __shfl_xor_sync(0xFFFFFFFFu, s1, off);
    }
    s0 += __ldg(&Gb[0]);
    s1 += __ldg(&Gb[1]);

    // softmax over 2 logits: overflow-safe sigmoid form
    const float g0 = 1.0f / (1.0f + __expf(s1 - s0));
    const float g1 = 1.0f - g0;

    // ---- blend + streaming stores (match L/R chunk layout) ----
    const size_t rowO = ((size_t)b * PAIRS + (size_t)p) * D4;
    #pragma unroll
    for (int j = 0; j < 4; j++) {
        #pragma unroll
        for (int k = 0; k < 2; k++) {
            const float4 Lv = L[2 * j + k];
            const float4 Rv = R[2 * j + k];
            float4 o;
            o.x = Lv.x * g0 + Rv.x * g1;
            o.y = Lv.y * g0 + Rv.y * g1;
            o.z = Lv.z * g0 + Rv.z * g1;
            o.w = Lv.w * g0 + Rv.w * g1;
            __stcs(&O4[rowO + j * 64 + 2 * lane + k], o);
        }
    }
}

extern "C" void kernel_launch(void* const* d_in, const int* in_sizes, int n_in,
                              void* d_out, int out_size)
{
    const float* X  = (const float*)d_in[0];
    const float* G  = (const float*)d_in[1];
    const float* Gb = (const float*)d_in[2];
    float* out = (float*)d_out;

    dim3 grid(NBLKX, BATCH);
    gated_cnn_v8_kernel<<<grid, 256>>>(X, G, Gb, out);
}

// round 11
// speedup vs baseline: 1.3307x; 1.3307x over previous
#include <cuda_runtime.h>

// GatedCNNLayer: X (16,4096,1024) f32, G (1024,2) f32, Gb (2,) f32
// out[b,p,:] = X[b,2p,:]*g0 + X[b,2p+2,:]*g1,
//   g = softmax(X[b,2p+1,:] @ G + Gb), p in [0,2047)
//
// FINAL (R3 verbatim — best of 10 variants, at the HBM roofline):
// Warp-per-pair, barrier-free steady state. Each warp owns one (b,p):
// 32 lanes x 8 float4 = 1024 columns. All 24 LDG.128 (mid+left+right) are
// front-batched for max MLP; gate reduce is warp-shuffle-only. G is staged
// to smem once per block. __ldcs on read-once mids, __stcs on the output
// stream to keep L2 free for the even-row (left/right) reuse.
//
// Roofline: 384MB required DRAM traffic @ ~6.2TB/s achieved => ~62us floor,
// which this kernel hits (ncu 56.6us kernel, DRAM 78%).

#define BATCH 16
#define SEQ   4096
#define DIM   1024
#define D4    (DIM / 4)      // 256 float4 per row
#define PAIRS 2047
#define WPB   8              // warps per block
#define NBLKX ((PAIRS + WPB - 1) / WPB)   // 256

__global__ __launch_bounds__(256)
void gated_cnn_warp_kernel(const float* __restrict__ X,
                           const float* __restrict__ G,
                           const float* __restrict__ Gb,
                           float* __restrict__ out)
{
    __shared__ float4 Gsh[2 * D4];   // 8 KB, (d,2) interleaved as float4 pairs

    const int t    = threadIdx.x;
    const int warp = t >> 5;
    const int lane = t & 31;

    // Stage G once per block (cold path, single barrier)
    {
        const float4* __restrict__ G4 = (const float4*)G;
        Gsh[t]       = G4[t];
        Gsh[t + 256] = G4[t + 256];
    }
    __syncthreads();

    const int p = blockIdx.x * WPB + warp;
    if (p >= PAIRS) return;
    const int b = blockIdx.y;

    const float4* __restrict__ X4 = (const float4*)X;
    float4* __restrict__ O4 = (float4*)out;

    const size_t rowL = ((size_t)b * SEQ + (size_t)(2 * p)) * D4;   // f4 units
    const size_t rowM = rowL + D4;
    const size_t rowR = rowM + D4;

    // ---- front-batched loads: 8 mid + 8 left + 8 right LDG.128 ----
    float4 M[8], L[8], R[8];
    #pragma unroll
    for (int j = 0; j < 8; j++) M[j] = __ldcs(&X4[rowM + j * 32 + lane]);
    #pragma unroll
    for (int j = 0; j < 8; j++) L[j] = X4[rowL + j * 32 + lane];
    #pragma unroll
    for (int j = 0; j < 8; j++) R[j] = X4[rowR + j * 32 + lane];

    // ---- gate logits from mids (smem-resident G) ----
    float s0 = 0.f, s1 = 0.f;
    #pragma unroll
    for (int j = 0; j < 8; j++) {
        const int idx = j * 32 + lane;
        const float4 m  = M[j];
        const float4 ga = Gsh[2 * idx];
        const float4 gc = Gsh[2 * idx + 1];
        s0 += m.x * ga.x + m.y * ga.z + m.z * gc.x + m.w * gc.z;
        s1 += m.x * ga.y + m.y * ga.w + m.z * gc.y + m.w * gc.w;
    }

    // ---- warp-only reduction (no block barrier) ----
    #pragma unroll
    for (int off = 16; off > 0; off >>= 1) {
        s0 += __shfl_xor_sync(0xFFFFFFFFu, s0, off);
        s1 += __shfl_xor_sync(0xFFFFFFFFu, s1, off);
    }
    s0 += __ldg(&Gb[0]);
    s1 += __ldg(&Gb[1]);

    // softmax over 2 logits: overflow-safe sigmoid form
    const float g0 = 1.0f / (1.0f + __expf(s1 - s0));
    const float g1 = 1.0f - g0;

    // ---- blend + streaming stores ----
    const size_t rowO = ((size_t)b * PAIRS + (size_t)p) * D4;
    #pragma unroll
    for (int j = 0; j < 8; j++) {
        float4 o;
        o.x = L[j].x * g0 + R[j].x * g1;
        o.y = L[j].y * g0 + R[j].y * g1;
        o.z = L[j].z * g0 + R[j].z * g1;
        o.w = L[j].w * g0 + R[j].w * g1;
        __stcs(&O4[rowO + j * 32 + lane], o);
    }
}

extern "C" void kernel_launch(void* const* d_in, const int* in_sizes, int n_in,
                              void* d_out, int out_size)
{
    const float* X  = (const float*)d_in[0];
    const float* G  = (const float*)d_in[1];
    const float* Gb = (const float*)d_in[2];
    float* out = (float*)d_out;

    dim3 grid(NBLKX, BATCH);
    gated_cnn_warp_kernel<<<grid, 256>>>(X, G, Gb, out);
}